// round 15
// baseline (speedup 1.0000x reference)
#include <cuda_runtime.h>
#include <cuda_bf16.h>
#include <math.h>
#include <stdint.h>

#define BB   4
#define LL   2048
#define EE   7
#define DD   512
#define HH   8
#define DH   64
#define PP   720
#define NL   2
#define UU   40
#define BH   (BB*HH)
#define MROWS (BB*LL)
#define SCALE 0.125f

typedef unsigned long long ull;
typedef uint32_t u32;
typedef __nv_bfloat16 bf16;

// ===================== warp-MMA helpers ====================================
__device__ __forceinline__ u32 smem_u32(const void* p) {
    u32 a;
    asm("{ .reg .u64 t; cvta.to.shared.u64 t, %1; cvt.u32.u64 %0, t; }"
        : "=r"(a) : "l"(p));
    return a;
}
__device__ __forceinline__ void cpasync16(u32 dst, const void* src) {
    asm volatile("cp.async.cg.shared.global [%0], [%1], 16;" :: "r"(dst), "l"(src));
}
#define CP_COMMIT() asm volatile("cp.async.commit_group;" ::: "memory")
#define CP_WAIT(n)  asm volatile("cp.async.wait_group %0;" :: "n"(n) : "memory")

#define LDM4(f, addr) \
    asm volatile("ldmatrix.sync.aligned.m8n8.x4.shared.b16 {%0,%1,%2,%3}, [%4];" \
        : "=r"((f)[0]), "=r"((f)[1]), "=r"((f)[2]), "=r"((f)[3]) : "r"(addr))

#define MMA(c, a, b0, b1) \
    asm volatile("mma.sync.aligned.m16n8k16.row.col.f32.bf16.bf16.f32 " \
        "{%0,%1,%2,%3}, {%4,%5,%6,%7}, {%8,%9}, {%0,%1,%2,%3};" \
        : "+f"((c)[0]), "+f"((c)[1]), "+f"((c)[2]), "+f"((c)[3]) \
        : "r"((a)[0]), "r"((a)[1]), "r"((a)[2]), "r"((a)[3]), "r"(b0), "r"(b1))

__device__ __forceinline__ void split1(float v, bf16& h, bf16& l) {
    h = __float2bfloat16(v);
    l = __float2bfloat16(v - __bfloat162float(h));
}

// term-major MMA body: 4 independent chains before any accumulator revisit
#define MMA_3TERM_P(acc, fa, fal, fbh, fbl, p) do { \
    MMA(acc[0][2*(p)],   fa[0],  fbh[0], fbh[2]); \
    MMA(acc[0][2*(p)+1], fa[0],  fbh[1], fbh[3]); \
    MMA(acc[1][2*(p)],   fa[1],  fbh[0], fbh[2]); \
    MMA(acc[1][2*(p)+1], fa[1],  fbh[1], fbh[3]); \
    MMA(acc[0][2*(p)],   fa[0],  fbl[0], fbl[2]); \
    MMA(acc[0][2*(p)+1], fa[0],  fbl[1], fbl[3]); \
    MMA(acc[1][2*(p)],   fa[1],  fbl[0], fbl[2]); \
    MMA(acc[1][2*(p)+1], fa[1],  fbl[1], fbl[3]); \
    MMA(acc[0][2*(p)],   fal[0], fbh[0], fbh[2]); \
    MMA(acc[0][2*(p)+1], fal[0], fbh[1], fbh[3]); \
    MMA(acc[1][2*(p)],   fal[1], fbh[0], fbh[2]); \
    MMA(acc[1][2*(p)+1], fal[1], fbh[1], fbh[3]); \
} while (0)

// ===================== scratch =============================================
__device__ float g_h [BB*LL*DD];
__device__ float g_q [BH*LL*DH];
__device__ float g_k [BH*LL*DH];
__device__ float g_v [BH*LL*DH];
__device__ float g_t2[BB*LL*DD];
__device__ float g_M [BH*LL];
__device__ int   g_idx[BH*UU];
__device__ float g_ksum [BH*DH];
__device__ float g_vmean[BH*DH];
__device__ float g_upd[BH*UU*DH];
__device__ float g_base[BB*DD];
__device__ bf16 g_ah[MROWS*DD];
__device__ bf16 g_al[MROWS*DD];
__device__ bf16 g_bh[MROWS*DD];
__device__ bf16 g_bl[MROWS*DD];
__device__ bf16 g_wh[5*DD*DD];
__device__ bf16 g_wl[5*DD*DD];
__device__ bf16 g_qh[BH*LL*DH];
__device__ bf16 g_kh[BH*LL*DH];

// ===================== weight transpose+split ==============================
__global__ void wsplit_kernel(const float* __restrict__ Wq, const float* __restrict__ Wk,
                              const float* __restrict__ Wv, const float* __restrict__ W1,
                              const float* __restrict__ W2,
                              bf16* __restrict__ wh, bf16* __restrict__ wl) {
    int slot = blockIdx.z;
    const float* W = (slot == 0) ? Wq : (slot == 1) ? Wk : (slot == 2) ? Wv
                   : (slot == 3) ? W1 : W2;
    __shared__ float ts[32][33];
    int n0 = blockIdx.x * 32, k0 = blockIdx.y * 32;
    int tx = threadIdx.x, ty = threadIdx.y;      // (32, 8)
    #pragma unroll
    for (int i = 0; i < 4; ++i)
        ts[ty + i*8][tx] = W[(size_t)(k0 + ty + i*8) * 512 + n0 + tx];
    __syncthreads();
    size_t so = (size_t)slot * DD * DD;
    #pragma unroll
    for (int i = 0; i < 4; ++i) {
        float v = ts[tx][ty + i*8];
        bf16 h, l; split1(v, h, l);
        size_t o = so + (size_t)(n0 + ty + i*8) * 512 + k0 + tx;
        wh[o] = h; wl[o] = l;
    }
}

// ===================== embedding (writes h + hi/lo split) ==================
__global__ void embed_kernel(const float* __restrict__ x,
                             const float* __restrict__ w,
                             const float* __restrict__ b,
                             float* __restrict__ out,
                             bf16* __restrict__ hi, bf16* __restrict__ lo) {
    int i = blockIdx.x * 256 + threadIdx.x;
    int row = i >> 9, n = i & 511;
    float acc = b[n];
    #pragma unroll
    for (int e = 0; e < EE; ++e) acc += x[row*EE + e] * w[e*DD + n];
    out[i] = acc;
    bf16 h, l; split1(acc, h, l);
    hi[i] = h; lo[i] = l;
}

// ===================== shared GEMM mainloop (macro) ========================
#define GK 32
#define GPAD 40
#define GARR (2*128*GPAD)

#define GEMM_MAINLOOP(AH, AL, WHp, WLp) \
    const u32 sAh = smem_u32(pAh), sAl = smem_u32(pAl); \
    const u32 sBh = smem_u32(pBh), sBl = smem_u32(pBl); \
    float acc[2][8][4]; \
    _Pragma("unroll") \
    for (int a = 0; a < 2; ++a) \
        _Pragma("unroll") \
        for (int n = 0; n < 8; ++n) \
            _Pragma("unroll") \
            for (int j = 0; j < 4; ++j) acc[a][n][j] = 0.f; \
    auto load_chunk = [&](int c, int buf) { \
        int kb = c * GK; \
        _Pragma("unroll") \
        for (int u = 0; u < 2; ++u) { \
            int i = tid + u * 256; \
            int r = i >> 2, j = (i & 3) * 8; \
            u32 doff = (u32)((buf * 128 * GPAD + r * GPAD + j) * 2); \
            cpasync16(sAh + doff, (AH) + (size_t)(m0 + r) * 512 + kb + j); \
            cpasync16(sAl + doff, (AL) + (size_t)(m0 + r) * 512 + kb + j); \
            cpasync16(sBh + doff, (WHp) + (size_t)(n0 + r) * 512 + kb + j); \
            cpasync16(sBl + doff, (WLp) + (size_t)(n0 + r) * 512 + kb + j); \
        } \
        CP_COMMIT(); \
    }; \
    load_chunk(0, 0); \
    for (int c = 0; c < 16; ++c) { \
        int buf = c & 1; \
        if (c < 15) load_chunk(c + 1, buf ^ 1); \
        if (c < 15) CP_WAIT(1); else CP_WAIT(0); \
        __syncthreads(); \
        u32 bofs = (u32)(buf * 128 * GPAD * 2); \
        _Pragma("unroll") \
        for (int s = 0; s < 2; ++s) { \
            int colb = (s * 16 + (lane >> 4) * 8) * 2; \
            u32 fa[2][4], fal[2][4]; \
            _Pragma("unroll") \
            for (int a = 0; a < 2; ++a) { \
                u32 ro = (u32)((wm * 32 + a * 16 + (lane & 15)) * GPAD * 2) + colb + bofs; \
                LDM4(fa[a],  sAh + ro); \
                LDM4(fal[a], sAl + ro); \
            } \
            _Pragma("unroll") \
            for (int p = 0; p < 4; ++p) { \
                u32 fbh[4], fbl[4]; \
                u32 ro = (u32)((wn * 64 + p * 16 + (lane & 15)) * GPAD * 2) + colb + bofs; \
                LDM4(fbh, sBh + ro); \
                LDM4(fbl, sBl + ro); \
                MMA_3TERM_P(acc, fa, fal, fbh, fbl, p); \
            } \
        } \
        __syncthreads(); \
    }

// ===================== generic GEMM =========================================
// MODE 0: plain fp32; 4: relu -> bf16 hi/lo row-major
template<int MODE>
__global__ __launch_bounds__(256, 2)
void gemm_mma(const bf16* __restrict__ ah, const bf16* __restrict__ al,
              const bf16* __restrict__ wh, const bf16* __restrict__ wl,
              const float* __restrict__ bias, float* __restrict__ out,
              bf16* __restrict__ outh, bf16* __restrict__ outl) {
    extern __shared__ bf16 sm[];
    bf16* pAh = sm;
    bf16* pAl = pAh + GARR;
    bf16* pBh = pAl + GARR;
    bf16* pBl = pBh + GARR;
    const int tid = threadIdx.x, lane = tid & 31, wid = tid >> 5;
    const int wm = wid & 3, wn = wid >> 2;
    const int m0 = blockIdx.x * 128, n0 = blockIdx.y * 128;

    GEMM_MAINLOOP(ah, al, wh, wl)

    int rg = m0 + wm * 32 + (lane >> 2);
    int cg = n0 + wn * 64 + (lane & 3) * 2;
    #pragma unroll
    for (int a = 0; a < 2; ++a)
        #pragma unroll
        for (int n = 0; n < 8; ++n) {
            int col = cg + n * 8;
            float2 bv = *(const float2*)&bias[col];
            #pragma unroll
            for (int hf = 0; hf < 2; ++hf) {
                int row = rg + a * 16 + hf * 8;
                float2 v = make_float2(acc[a][n][hf*2] + bv.x, acc[a][n][hf*2+1] + bv.y);
                if (MODE == 4) {
                    v.x = fmaxf(v.x, 0.f); v.y = fmaxf(v.y, 0.f);
                    bf16 hx, lx, hy, ly;
                    split1(v.x, hx, lx); split1(v.y, hy, ly);
                    __nv_bfloat162 hv = __halves2bfloat162(hx, hy);
                    __nv_bfloat162 lv = __halves2bfloat162(lx, ly);
                    size_t o = (size_t)row * 512 + col;
                    *(u32*)&outh[o] = *(u32*)&hv;
                    *(u32*)&outl[o] = *(u32*)&lv;
                } else {
                    *(float2*)&out[(size_t)row * 512 + col] = v;
                }
            }
        }
}

// ===================== fused QKV GEMM =======================================
// grid (64, 12): slot = by>>2 (0:Q 1:K 2:V), n-tile = by&3
__global__ __launch_bounds__(256, 2)
void qkv_mma(const bf16* __restrict__ ah, const bf16* __restrict__ al,
             const bf16* __restrict__ wh, const bf16* __restrict__ wl,
             const float* __restrict__ bq, const float* __restrict__ bk,
             const float* __restrict__ bv,
             float* __restrict__ outq, float* __restrict__ outk, float* __restrict__ outv,
             bf16* __restrict__ outqh, bf16* __restrict__ outkh) {
    extern __shared__ bf16 sm[];
    bf16* pAh = sm;
    bf16* pAl = pAh + GARR;
    bf16* pBh = pAl + GARR;
    bf16* pBl = pBh + GARR;
    const int tid = threadIdx.x, lane = tid & 31, wid = tid >> 5;
    const int wm = wid & 3, wn = wid >> 2;
    const int slot = blockIdx.y >> 2;
    const int m0 = blockIdx.x * 128, n0 = (blockIdx.y & 3) * 128;
    const bf16* whp = wh + (size_t)slot * DD * DD;
    const bf16* wlp = wl + (size_t)slot * DD * DD;
    const float* bias = (slot == 0) ? bq : (slot == 1) ? bk : bv;
    float* out = (slot == 0) ? outq : (slot == 1) ? outk : outv;
    bf16* outh = (slot == 0) ? outqh : outkh;

    GEMM_MAINLOOP(ah, al, whp, wlp)

    int rg = m0 + wm * 32 + (lane >> 2);
    int cg = n0 + wn * 64 + (lane & 3) * 2;
    #pragma unroll
    for (int a = 0; a < 2; ++a)
        #pragma unroll
        for (int n = 0; n < 8; ++n) {
            int col = cg + n * 8;
            float2 bvv = *(const float2*)&bias[col];
            #pragma unroll
            for (int hf = 0; hf < 2; ++hf) {
                int row = rg + a * 16 + hf * 8;
                float2 v = make_float2(acc[a][n][hf*2] + bvv.x, acc[a][n][hf*2+1] + bvv.y);
                int hh = col >> 6, dh = col & 63, b_ = row >> 11, l_ = row & 2047;
                size_t o = (((size_t)(b_*HH + hh))*LL + l_)*DH + dh;
                *(float2*)&out[o] = v;
                if (slot < 2) {
                    __nv_bfloat162 hv = __floats2bfloat162_rn(v.x, v.y);
                    *(u32*)&outh[o] = *(u32*)&hv;
                }
            }
        }
}

// ===================== M(q): 1-term bf16 warp MMA ==========================
#define MPAD 72
__global__ __launch_bounds__(256, 2)
void m_mma(const bf16* __restrict__ qh, const bf16* __restrict__ kh,
           const float* __restrict__ qf, const float* __restrict__ ksum,
           float* __restrict__ Mout) {
    extern __shared__ bf16 sm[];
    bf16* pK = sm;
    float* red = (float*)(pK + 2*128*MPAD);
    const int tid = threadIdx.x, lane = tid & 31, wid = tid >> 5;
    const int wm = wid & 3, wn = wid >> 2;
    const int bh = blockIdx.y, q0 = blockIdx.x * 128;
    const bf16* qhb = qh + (size_t)bh * LL * DH;
    const bf16* khb = kh + (size_t)bh * LL * DH;
    const u32 sK = smem_u32(pK);
    const u32 sQ = sK + 128 * MPAD * 2;

    auto load_k = [&](int t, int buf) {
        #pragma unroll
        for (int u = 0; u < 4; ++u) {
            int i = tid + u * 256;
            int r = i >> 3, j = (i & 7) * 8;
            cpasync16(sK + (u32)((buf * 128 * MPAD + r * MPAD + j) * 2),
                      khb + (size_t)(t * 128 + r) * 64 + j);
        }
        CP_COMMIT();
    };

    load_k(0, 0);
    #pragma unroll
    for (int u = 0; u < 4; ++u) {
        int i = tid + u * 256;
        int r = i >> 3, j = (i & 7) * 8;
        cpasync16(sQ + (u32)((r * MPAD + j) * 2), qhb + (size_t)(q0 + r) * 64 + j);
    }
    CP_COMMIT();
    CP_WAIT(0);
    __syncthreads();

    u32 fq[4][2][4];
    #pragma unroll
    for (int s = 0; s < 4; ++s) {
        int colb = (s * 16 + (lane >> 4) * 8) * 2;
        #pragma unroll
        for (int a = 0; a < 2; ++a) {
            u32 ro = (u32)((wm * 32 + a * 16 + (lane & 15)) * MPAD * 2) + colb;
            LDM4(fq[s][a], sQ + ro);
        }
    }
    __syncthreads();

    float rmax[2][2];
    rmax[0][0] = rmax[0][1] = rmax[1][0] = rmax[1][1] = -INFINITY;

    for (int t = 0; t < 16; ++t) {
        int buf = t & 1;
        if (t < 15) load_k(t + 1, buf ^ 1);
        if (t < 15) CP_WAIT(1); else CP_WAIT(0);
        __syncthreads();
        float acc[2][8][4];
        #pragma unroll
        for (int a = 0; a < 2; ++a)
            #pragma unroll
            for (int n = 0; n < 8; ++n)
                #pragma unroll
                for (int j = 0; j < 4; ++j) acc[a][n][j] = 0.f;
        u32 bofs = (u32)(buf * 128 * MPAD * 2);
        #pragma unroll
        for (int s = 0; s < 4; ++s) {
            int colb = (s * 16 + (lane >> 4) * 8) * 2;
            #pragma unroll
            for (int p = 0; p < 4; ++p) {
                u32 fb[4];
                u32 ro = (u32)((wn * 64 + p * 16 + (lane & 15)) * MPAD * 2) + colb + bofs;
                LDM4(fb, sK + ro);
                #pragma unroll
                for (int a = 0; a < 2; ++a) {
                    MMA(acc[a][2*p],   fq[s][a], fb[0], fb[2]);
                    MMA(acc[a][2*p+1], fq[s][a], fb[1], fb[3]);
                }
            }
        }
        #pragma unroll
        for (int a = 0; a < 2; ++a)
            #pragma unroll
            for (int n = 0; n < 8; ++n) {
                rmax[a][0] = fmaxf(rmax[a][0], fmaxf(acc[a][n][0], acc[a][n][1]));
                rmax[a][1] = fmaxf(rmax[a][1], fmaxf(acc[a][n][2], acc[a][n][3]));
            }
        __syncthreads();
    }

    #pragma unroll
    for (int a = 0; a < 2; ++a)
        #pragma unroll
        for (int hf = 0; hf < 2; ++hf) {
            float v = rmax[a][hf];
            v = fmaxf(v, __shfl_xor_sync(0xffffffffu, v, 1));
            v = fmaxf(v, __shfl_xor_sync(0xffffffffu, v, 2));
            rmax[a][hf] = v;
        }
    if ((lane & 3) == 0) {
        #pragma unroll
        for (int a = 0; a < 2; ++a)
            #pragma unroll
            for (int hf = 0; hf < 2; ++hf)
                red[wn * 128 + wm * 32 + a * 16 + hf * 8 + (lane >> 2)] = rmax[a][hf];
    }
    __syncthreads();
    if (tid < 128) {
        float m = fmaxf(red[tid], red[128 + tid]);
        const float* ks = ksum + bh * DH;
        const float* qrow = qf + ((size_t)bh * LL + q0 + tid) * DH;
        float dot = 0.f;
        #pragma unroll
        for (int d = 0; d < 64; ++d) dot += qrow[d] * ks[d];
        Mout[bh * LL + q0 + tid] = (m - dot * (1.f / LL)) * SCALE;
    }
}

// ===================== per-(b,h) sums ======================================
__global__ void sums_kernel(const float* __restrict__ k, const float* __restrict__ v,
                            float* __restrict__ ksum, float* __restrict__ vmean) {
    int bh = blockIdx.x, tid = threadIdx.x;
    int d = tid & 63, c = tid >> 6;
    const float* kb = k + (size_t)bh * LL * DH + d;
    const float* vb = v + (size_t)bh * LL * DH + d;
    float ks = 0.f, vs = 0.f;
    for (int l = c; l < LL; l += 4) { ks += kb[(size_t)l*DH]; vs += vb[(size_t)l*DH]; }
    __shared__ float rk[4][64], rv[4][64];
    rk[c][d] = ks; rv[c][d] = vs;
    __syncthreads();
    if (tid < 64) {
        float a = rk[0][tid] + rk[1][tid] + rk[2][tid] + rk[3][tid];
        float m = rv[0][tid] + rv[1][tid] + rv[2][tid] + rv[3][tid];
        ksum [bh*DH + tid] = a;
        vmean[bh*DH + tid] = m * (1.f / LL);
    }
}

// ===================== top-U selection =====================================
__global__ void topk_kernel(const float* __restrict__ M, int* __restrict__ idxout) {
    int bh = blockIdx.x, tid = threadIdx.x;
    __shared__ float sm[LL];
    __shared__ float bvv[256];
    __shared__ int   bii[256];
    for (int l = tid; l < LL; l += 256) sm[l] = M[bh*LL + l];
    __syncthreads();
    for (int it = 0; it < UU; ++it) {
        float best = -INFINITY; int bidx = LL;
        for (int l = tid; l < LL; l += 256) {
            float v = sm[l];
            if (v > best || (v == best && l < bidx)) { best = v; bidx = l; }
        }
        bvv[tid] = best; bii[tid] = bidx;
        __syncthreads();
        for (int s = 128; s > 0; s >>= 1) {
            if (tid < s) {
                if (bvv[tid+s] > bvv[tid] || (bvv[tid+s] == bvv[tid] && bii[tid+s] < bii[tid])) {
                    bvv[tid] = bvv[tid+s]; bii[tid] = bii[tid+s];
                }
            }
            __syncthreads();
        }
        if (tid == 0) { idxout[bh*UU + it] = bii[0]; sm[bii[0]] = -INFINITY; }
        __syncthreads();
    }
}

// ===================== attention (8 queries / block) =======================
__global__ __launch_bounds__(256, 2)
void attn_kernel(const float* __restrict__ q, const float* __restrict__ k,
                 const float* __restrict__ v, const int* __restrict__ idx,
                 float* __restrict__ upd) {
    extern __shared__ float sbuf[];
    float* sc   = sbuf;
    float* qv   = sbuf + 8*2048;
    float* red  = qv + 512;
    float* sinv = red + 2048;
    int bh = blockIdx.x, u0 = blockIdx.y * 8;
    int tid = threadIdx.x;
    const float* kb = k + (size_t)bh * LL * DH;
    const float* vb = v + (size_t)bh * LL * DH;

    for (int i = tid; i < 8*64; i += 256) {
        int u = i >> 6, d = i & 63;
        int lq = idx[bh*UU + u0 + u];
        qv[i] = q[((size_t)bh*LL + lq)*DH + d];
    }
    __syncthreads();

    for (int l = tid; l < LL; l += 256) {
        const float4* kr = (const float4*)(kb + (size_t)l*DH);
        float acc[8];
        #pragma unroll
        for (int u = 0; u < 8; ++u) acc[u] = 0.f;
        #pragma unroll
        for (int t = 0; t < 16; ++t) {
            float4 kv = kr[t];
            #pragma unroll
            for (int u = 0; u < 8; ++u) {
                float4 qq = *(const float4*)&qv[u*64 + t*4];
                acc[u] += kv.x*qq.x + kv.y*qq.y + kv.z*qq.z + kv.w*qq.w;
            }
        }
        #pragma unroll
        for (int u = 0; u < 8; ++u) sc[u*2048 + l] = acc[u] * SCALE;
    }
    __syncthreads();

    {
        int u = tid >> 5, lane = tid & 31;
        float m = -INFINITY;
        for (int l = lane; l < LL; l += 32) m = fmaxf(m, sc[u*2048 + l]);
        #pragma unroll
        for (int o = 16; o > 0; o >>= 1) m = fmaxf(m, __shfl_xor_sync(0xffffffffu, m, o));
        float s = 0.f;
        for (int l = lane; l < LL; l += 32) {
            float e = __expf(sc[u*2048 + l] - m);
            sc[u*2048 + l] = e; s += e;
        }
        #pragma unroll
        for (int o = 16; o > 0; o >>= 1) s += __shfl_xor_sync(0xffffffffu, s, o);
        if (lane == 0) sinv[u] = 1.f / s;
    }
    __syncthreads();

    int d = tid & 63, lc = tid >> 6;
    float acc[8];
    #pragma unroll
    for (int u = 0; u < 8; ++u) acc[u] = 0.f;
    for (int l = lc; l < LL; l += 4) {
        float vv = vb[(size_t)l*DH + d];
        #pragma unroll
        for (int u = 0; u < 8; ++u) acc[u] += sc[u*2048 + l] * vv;
    }
    #pragma unroll
    for (int u = 0; u < 8; ++u) red[(lc*8 + u)*64 + d] = acc[u];
    __syncthreads();
    if (tid < 64) {
        #pragma unroll
        for (int u = 0; u < 8; ++u) {
            float t = red[u*64 + tid] + red[(8+u)*64 + tid] +
                      red[(16+u)*64 + tid] + red[(24+u)*64 + tid];
            upd[((size_t)bh*UU + u0 + u)*DH + tid] = t * sinv[u];
        }
    }
}

// ===================== Wo via base + sparse corrections ====================
__global__ void base_kernel(const float* __restrict__ vmean, const float* __restrict__ Wo,
                            const float* __restrict__ bo, float* __restrict__ base) {
    int b = blockIdx.x, n = threadIdx.x;
    const float* vm = vmean + b * 512;
    float acc = bo[n];
    for (int kk = 0; kk < 512; ++kk)
        acc += vm[kk] * Wo[(size_t)kk*512 + n];
    base[b*512 + n] = acc;
}

__global__ void corr_kernel(const float* __restrict__ upd, const float* __restrict__ vmean,
                            const float* __restrict__ Wo, const int* __restrict__ idx,
                            float* __restrict__ delta) {
    int blk = blockIdx.x;
    int bh = blk / UU, u = blk % UU;
    int h = bh & 7, b = bh >> 3;
    __shared__ float du[64];
    int tid = threadIdx.x;
    if (tid < 64) du[tid] = upd[(size_t)blk*64 + tid] - vmean[bh*64 + tid];
    __syncthreads();
    int l = idx[bh*UU + u];
    float* drow = delta + ((size_t)b*LL + l)*DD;
    const float* wrow = Wo + (size_t)h*64*512;
    #pragma unroll
    for (int half = 0; half < 2; ++half) {
        int n = tid + half*256;
        float acc = 0.f;
        #pragma unroll 8
        for (int d = 0; d < 64; ++d) acc += du[d] * wrow[(size_t)d*512 + n];
        atomicAdd(&drow[n], acc);
    }
}

// ===================== residual + LayerNorm (fused splits) =================
__global__ void addln_base_kernel(float* h, const float* __restrict__ delta,
                                  const float* __restrict__ base,
                                  const float* __restrict__ g, const float* __restrict__ b,
                                  bf16* __restrict__ sh, bf16* __restrict__ sl) {
    int row = blockIdx.x, tid = threadIdx.x;
    int bb_ = row >> 11;
    float* hr = h + (size_t)row * DD;
    const float* dr = delta + (size_t)row * DD;
    const float* br = base + bb_ * DD;
    __shared__ float rbuf[8];
    __shared__ float sh_mean, sh_var;
    float s0 = hr[tid]       + dr[tid]       + br[tid];
    float s1 = hr[tid + 256] + dr[tid + 256] + br[tid + 256];
    float s = s0 + s1;
    for (int o = 16; o > 0; o >>= 1) s += __shfl_down_sync(0xffffffffu, s, o);
    if ((tid & 31) == 0) rbuf[tid >> 5] = s;
    __syncthreads();
    if (tid == 0) {
        float t = 0.f;
        #pragma unroll
        for (int i = 0; i < 8; ++i) t += rbuf[i];
        sh_mean = t * (1.f / DD);
    }
    __syncthreads();
    float mval = sh_mean;
    float d0 = s0 - mval, d1 = s1 - mval;
    float vv = d0*d0 + d1*d1;
    for (int o = 16; o > 0; o >>= 1) vv += __shfl_down_sync(0xffffffffu, vv, o);
    if ((tid & 31) == 0) rbuf[tid >> 5] = vv;
    __syncthreads();
    if (tid == 0) {
        float t = 0.f;
        #pragma unroll
        for (int i = 0; i < 8; ++i) t += rbuf[i];
        sh_var = t * (1.f / DD);
    }
    __syncthreads();
    float inv = rsqrtf(sh_var + 1e-5f);
    float o0 = d0 * inv * g[tid]       + b[tid];
    float o1 = d1 * inv * g[tid + 256] + b[tid + 256];
    hr[tid] = o0; hr[tid + 256] = o1;
    bf16 hh, ll;
    split1(o0, hh, ll); sh[(size_t)row*DD + tid] = hh;       sl[(size_t)row*DD + tid] = ll;
    split1(o1, hh, ll); sh[(size_t)row*DD + tid + 256] = hh; sl[(size_t)row*DD + tid + 256] = ll;
}

template<int SPLIT>
__global__ void addln_kernel(float* h, const float* __restrict__ a,
                             const float* __restrict__ g, const float* __restrict__ b,
                             bf16* __restrict__ sh, bf16* __restrict__ sl) {
    int row = blockIdx.x, tid = threadIdx.x;
    float* hr = h + (size_t)row * DD;
    const float* ar = a + (size_t)row * DD;
    __shared__ float rbuf[8];
    __shared__ float sh_mean, sh_var;
    float s0 = hr[tid]       + ar[tid];
    float s1 = hr[tid + 256] + ar[tid + 256];
    float s = s0 + s1;
    for (int o = 16; o > 0; o >>= 1) s += __shfl_down_sync(0xffffffffu, s, o);
    if ((tid & 31) == 0) rbuf[tid >> 5] = s;
    __syncthreads();
    if (tid == 0) {
        float t = 0.f;
        #pragma unroll
        for (int i = 0; i < 8; ++i) t += rbuf[i];
        sh_mean = t * (1.f / DD);
    }
    __syncthreads();
    float mval = sh_mean;
    float d0 = s0 - mval, d1 = s1 - mval;
    float vv = d0*d0 + d1*d1;
    for (int o = 16; o > 0; o >>= 1) vv += __shfl_down_sync(0xffffffffu, vv, o);
    if ((tid & 31) == 0) rbuf[tid >> 5] = vv;
    __syncthreads();
    if (tid == 0) {
        float t = 0.f;
        #pragma unroll
        for (int i = 0; i < 8; ++i) t += rbuf[i];
        sh_var = t * (1.f / DD);
    }
    __syncthreads();
    float inv = rsqrtf(sh_var + 1e-5f);
    float o0 = d0 * inv * g[tid]       + b[tid];
    float o1 = d1 * inv * g[tid + 256] + b[tid + 256];
    hr[tid] = o0; hr[tid + 256] = o1;
    if (SPLIT) {
        bf16 hh, ll;
        split1(o0, hh, ll); sh[(size_t)row*DD + tid] = hh;       sl[(size_t)row*DD + tid] = ll;
        split1(o1, hh, ll); sh[(size_t)row*DD + tid + 256] = hh; sl[(size_t)row*DD + tid + 256] = ll;
    }
}

// ===================== final projection ====================================
__global__ void proj_kernel(const float* __restrict__ h, const float* __restrict__ pw,
                            const float* __restrict__ pb, float* __restrict__ out) {
    int bp = blockIdx.x;
    int b = bp / PP, p = bp % PP;
    int l = LL - PP + p;
    int tid = threadIdx.x;
    const float* hr = h + ((size_t)b*LL + l)*DD;
    float acc[EE];
    #pragma unroll
    for (int e = 0; e < EE; ++e) acc[e] = 0.f;
    for (int kk = tid; kk < DD; kk += 64) {
        float hv = hr[kk];
        #pragma unroll
        for (int e = 0; e < EE; ++e) acc[e] += hv * pw[kk*EE + e];
    }
    __shared__ float red[EE][64];
    #pragma unroll
    for (int e = 0; e < EE; ++e) red[e][tid] = acc[e];
    __syncthreads();
    if (tid < EE) {
        float t = 0.f;
        for (int i = 0; i < 64; ++i) t += red[tid][i];
        out[(size_t)bp * EE + tid] = t + pb[tid];
    }
}

// ===================== host driver =========================================
#define SMEM_G_BYTES (4 * GARR * 2)
#define SMEM_M_BYTES (2*128*MPAD*2 + 1024)
#define SMEM_A_BYTES ((8*2048 + 512 + 2048 + 8) * 4)

extern "C" void kernel_launch(void* const* d_in, const int* in_sizes, int n_in,
                              void* d_out, int out_size) {
    const float* x      = (const float*)d_in[0];
    const float* emb_w  = (const float*)d_in[1];
    const float* emb_b  = (const float*)d_in[2];
    const float* Wq     = (const float*)d_in[3];
    const float* bq     = (const float*)d_in[4];
    const float* Wk     = (const float*)d_in[5];
    const float* bk     = (const float*)d_in[6];
    const float* Wv     = (const float*)d_in[7];
    const float* bv     = (const float*)d_in[8];
    const float* Wo     = (const float*)d_in[9];
    const float* bo     = (const float*)d_in[10];
    const float* W1     = (const float*)d_in[11];
    const float* b1     = (const float*)d_in[12];
    const float* W2     = (const float*)d_in[13];
    const float* b2     = (const float*)d_in[14];
    const float* ln1_g  = (const float*)d_in[15];
    const float* ln1_b  = (const float*)d_in[16];
    const float* ln2_g  = (const float*)d_in[17];
    const float* ln2_b  = (const float*)d_in[18];
    const float* proj_w = (const float*)d_in[19];
    const float* proj_b = (const float*)d_in[20];

    static float *p_h = nullptr, *p_q, *p_k, *p_v, *p_t2, *p_M,
                 *p_ksum, *p_vmean, *p_upd, *p_base;
    static bf16 *p_ah, *p_al, *p_bh, *p_bl, *p_wh, *p_wl, *p_qh, *p_kh;
    static int *p_idx;
    if (!p_h) {
        cudaGetSymbolAddress((void**)&p_h,    g_h);
        cudaGetSymbolAddress((void**)&p_q,    g_q);
        cudaGetSymbolAddress((void**)&p_k,    g_k);
        cudaGetSymbolAddress((void**)&p_v,    g_v);
        cudaGetSymbolAddress((void**)&p_t2,   g_t2);
        cudaGetSymbolAddress((void**)&p_M,    g_M);
        cudaGetSymbolAddress((void**)&p_idx,  g_idx);
        cudaGetSymbolAddress((void**)&p_ksum, g_ksum);
        cudaGetSymbolAddress((void**)&p_vmean,g_vmean);
        cudaGetSymbolAddress((void**)&p_upd,  g_upd);
        cudaGetSymbolAddress((void**)&p_base, g_base);
        cudaGetSymbolAddress((void**)&p_ah,   g_ah);
        cudaGetSymbolAddress((void**)&p_al,   g_al);
        cudaGetSymbolAddress((void**)&p_bh,   g_bh);
        cudaGetSymbolAddress((void**)&p_bl,   g_bl);
        cudaGetSymbolAddress((void**)&p_wh,   g_wh);
        cudaGetSymbolAddress((void**)&p_wl,   g_wl);
        cudaGetSymbolAddress((void**)&p_qh,   g_qh);
        cudaGetSymbolAddress((void**)&p_kh,   g_kh);
        cudaFuncSetAttribute(gemm_mma<0>, cudaFuncAttributeMaxDynamicSharedMemorySize, SMEM_G_BYTES);
        cudaFuncSetAttribute(gemm_mma<4>, cudaFuncAttributeMaxDynamicSharedMemorySize, SMEM_G_BYTES);
        cudaFuncSetAttribute(qkv_mma,     cudaFuncAttributeMaxDynamicSharedMemorySize, SMEM_G_BYTES);
        cudaFuncSetAttribute(m_mma,       cudaFuncAttributeMaxDynamicSharedMemorySize, SMEM_M_BYTES);
        cudaFuncSetAttribute(attn_kernel, cudaFuncAttributeMaxDynamicSharedMemorySize, SMEM_A_BYTES);
    }

    embed_kernel<<<(BB*LL*DD)/256, 256>>>(x, emb_w, emb_b, p_h, p_ah, p_al);

    dim3 gg(MROWS/128, DD/128);
    dim3 wsg(16, 16, 5), wsb(32, 8);
    for (int il = 0; il < NL; ++il) {
        const size_t wo = (size_t)il * DD * DD;
        const size_t boff = (size_t)il * DD;
        wsplit_kernel<<<wsg, wsb>>>(Wq + wo, Wk + wo, Wv + wo, W1 + wo, W2 + wo, p_wh, p_wl);
        qkv_mma<<<dim3(MROWS/128, 12), 256, SMEM_G_BYTES>>>(
            p_ah, p_al, p_wh, p_wl, bq + boff, bk + boff, bv + boff,
            p_q, p_k, p_v, p_qh, p_kh);
        sums_kernel<<<BH, 256>>>(p_k, p_v, p_ksum, p_vmean);
        m_mma<<<dim3(LL/128, BH), 256, SMEM_M_BYTES>>>(p_qh, p_kh, p_q, p_ksum, p_M);
        topk_kernel<<<BH, 256>>>(p_M, p_idx);
        attn_kernel<<<dim3(BH, UU/8), 256, SMEM_A_BYTES>>>(p_q, p_k, p_v, p_idx, p_upd);
        base_kernel<<<BB, 512>>>(p_vmean, Wo + wo, bo + boff, p_base);
        cudaMemsetAsync(p_t2, 0, (size_t)BB*LL*DD*sizeof(float));
        corr_kernel<<<BH*UU, 256>>>(p_upd, p_vmean, Wo + wo, p_idx, p_t2);
        addln_base_kernel<<<MROWS, 256>>>(p_h, p_t2, p_base, ln1_g + boff, ln1_b + boff, p_ah, p_al);
        gemm_mma<4><<<gg, 256, SMEM_G_BYTES>>>(p_ah, p_al, p_wh + 3*DD*DD, p_wl + 3*DD*DD, b1 + boff, p_t2, p_bh, p_bl);
        gemm_mma<0><<<gg, 256, SMEM_G_BYTES>>>(p_bh, p_bl, p_wh + 4*DD*DD, p_wl + 4*DD*DD, b2 + boff, p_t2, p_bh, p_bl);
        if (il < NL - 1)
            addln_kernel<1><<<MROWS, 256>>>(p_h, p_t2, ln2_g + boff, ln2_b + boff, p_ah, p_al);
        else
            addln_kernel<0><<<MROWS, 256>>>(p_h, p_t2, ln2_g + boff, ln2_b + boff, p_ah, p_al);
    }

    proj_kernel<<<BB*PP, 64>>>(p_h, proj_w, proj_b, (float*)d_out);
}

// round 16
// speedup vs baseline: 1.2209x; 1.2209x over previous
#include <cuda_runtime.h>
#include <cuda_bf16.h>
#include <math.h>
#include <stdint.h>

#define BB   4
#define LL   2048
#define EE   7
#define DD   512
#define HH   8
#define DH   64
#define PP   720
#define NL   2
#define UU   40
#define BH   (BB*HH)
#define MROWS (BB*LL)
#define SCALE 0.125f

typedef unsigned long long ull;
typedef uint32_t u32;
typedef __nv_bfloat16 bf16;

// ===================== warp-MMA helpers ====================================
__device__ __forceinline__ u32 smem_u32(const void* p) {
    u32 a;
    asm("{ .reg .u64 t; cvta.to.shared.u64 t, %1; cvt.u32.u64 %0, t; }"
        : "=r"(a) : "l"(p));
    return a;
}
__device__ __forceinline__ void cpasync16(u32 dst, const void* src) {
    asm volatile("cp.async.cg.shared.global [%0], [%1], 16;" :: "r"(dst), "l"(src));
}
#define CP_COMMIT() asm volatile("cp.async.commit_group;" ::: "memory")
#define CP_WAIT(n)  asm volatile("cp.async.wait_group %0;" :: "n"(n) : "memory")

#define LDM4(f, addr) \
    asm volatile("ldmatrix.sync.aligned.m8n8.x4.shared.b16 {%0,%1,%2,%3}, [%4];" \
        : "=r"((f)[0]), "=r"((f)[1]), "=r"((f)[2]), "=r"((f)[3]) : "r"(addr))

#define MMA(c, a, b0, b1) \
    asm volatile("mma.sync.aligned.m16n8k16.row.col.f32.bf16.bf16.f32 " \
        "{%0,%1,%2,%3}, {%4,%5,%6,%7}, {%8,%9}, {%0,%1,%2,%3};" \
        : "+f"((c)[0]), "+f"((c)[1]), "+f"((c)[2]), "+f"((c)[3]) \
        : "r"((a)[0]), "r"((a)[1]), "r"((a)[2]), "r"((a)[3]), "r"(b0), "r"(b1))

__device__ __forceinline__ void split1(float v, bf16& h, bf16& l) {
    h = __float2bfloat16(v);
    l = __float2bfloat16(v - __bfloat162float(h));
}

// term-major MMA body: 4 independent chains before any accumulator revisit
#define MMA_3TERM_P(acc, fa, fal, fbh, fbl, p) do { \
    MMA(acc[0][2*(p)],   fa[0],  fbh[0], fbh[2]); \
    MMA(acc[0][2*(p)+1], fa[0],  fbh[1], fbh[3]); \
    MMA(acc[1][2*(p)],   fa[1],  fbh[0], fbh[2]); \
    MMA(acc[1][2*(p)+1], fa[1],  fbh[1], fbh[3]); \
    MMA(acc[0][2*(p)],   fa[0],  fbl[0], fbl[2]); \
    MMA(acc[0][2*(p)+1], fa[0],  fbl[1], fbl[3]); \
    MMA(acc[1][2*(p)],   fa[1],  fbl[0], fbl[2]); \
    MMA(acc[1][2*(p)+1], fa[1],  fbl[1], fbl[3]); \
    MMA(acc[0][2*(p)],   fal[0], fbh[0], fbh[2]); \
    MMA(acc[0][2*(p)+1], fal[0], fbh[1], fbh[3]); \
    MMA(acc[1][2*(p)],   fal[1], fbh[0], fbh[2]); \
    MMA(acc[1][2*(p)+1], fal[1], fbh[1], fbh[3]); \
} while (0)

// ===================== scratch =============================================
__device__ float g_h [BB*LL*DD];
__device__ float g_q [BH*LL*DH];
__device__ float g_k [BH*LL*DH];
__device__ float g_v [BH*LL*DH];
__device__ float g_t2[BB*LL*DD];
__device__ float g_M [BH*LL];
__device__ int   g_idx[BH*UU];
__device__ float g_ksum [BH*DH];
__device__ float g_vsum [BH*DH];
__device__ float g_vmean[BH*DH];
__device__ float g_upd[BH*UU*DH];
__device__ float g_base[BB*DD];
__device__ bf16 g_ah[MROWS*DD];
__device__ bf16 g_al[MROWS*DD];
__device__ bf16 g_bh[MROWS*DD];
__device__ bf16 g_bl[MROWS*DD];
__device__ bf16 g_wh[5*DD*DD];
__device__ bf16 g_wl[5*DD*DD];
__device__ bf16 g_qh[BH*LL*DH];
__device__ bf16 g_kh[BH*LL*DH];

// ===================== weight transpose+split ==============================
__global__ void wsplit_kernel(const float* __restrict__ Wq, const float* __restrict__ Wk,
                              const float* __restrict__ Wv, const float* __restrict__ W1,
                              const float* __restrict__ W2,
                              bf16* __restrict__ wh, bf16* __restrict__ wl) {
    int slot = blockIdx.z;
    const float* W = (slot == 0) ? Wq : (slot == 1) ? Wk : (slot == 2) ? Wv
                   : (slot == 3) ? W1 : W2;
    __shared__ float ts[32][33];
    int n0 = blockIdx.x * 32, k0 = blockIdx.y * 32;
    int tx = threadIdx.x, ty = threadIdx.y;      // (32, 8)
    #pragma unroll
    for (int i = 0; i < 4; ++i)
        ts[ty + i*8][tx] = W[(size_t)(k0 + ty + i*8) * 512 + n0 + tx];
    __syncthreads();
    size_t so = (size_t)slot * DD * DD;
    #pragma unroll
    for (int i = 0; i < 4; ++i) {
        float v = ts[tx][ty + i*8];
        bf16 h, l; split1(v, h, l);
        size_t o = so + (size_t)(n0 + ty + i*8) * 512 + k0 + tx;
        wh[o] = h; wl[o] = l;
    }
}

// ===================== embedding (writes h + hi/lo split) ==================
__global__ void embed_kernel(const float* __restrict__ x,
                             const float* __restrict__ w,
                             const float* __restrict__ b,
                             float* __restrict__ out,
                             bf16* __restrict__ hi, bf16* __restrict__ lo) {
    int i = blockIdx.x * 256 + threadIdx.x;
    int row = i >> 9, n = i & 511;
    float acc = b[n];
    #pragma unroll
    for (int e = 0; e < EE; ++e) acc += x[row*EE + e] * w[e*DD + n];
    out[i] = acc;
    bf16 h, l; split1(acc, h, l);
    hi[i] = h; lo[i] = l;
}

// ===================== shared GEMM mainloop (macro) ========================
#define GK 32
#define GPAD 40
#define GARR (2*128*GPAD)

#define GEMM_MAINLOOP(AH, AL, WHp, WLp) \
    const u32 sAh = smem_u32(pAh), sAl = smem_u32(pAl); \
    const u32 sBh = smem_u32(pBh), sBl = smem_u32(pBl); \
    float acc[2][8][4]; \
    _Pragma("unroll") \
    for (int a = 0; a < 2; ++a) \
        _Pragma("unroll") \
        for (int n = 0; n < 8; ++n) \
            _Pragma("unroll") \
            for (int j = 0; j < 4; ++j) acc[a][n][j] = 0.f; \
    auto load_chunk = [&](int c, int buf) { \
        int kb = c * GK; \
        _Pragma("unroll") \
        for (int u = 0; u < 2; ++u) { \
            int i = tid + u * 256; \
            int r = i >> 2, j = (i & 3) * 8; \
            u32 doff = (u32)((buf * 128 * GPAD + r * GPAD + j) * 2); \
            cpasync16(sAh + doff, (AH) + (size_t)(m0 + r) * 512 + kb + j); \
            cpasync16(sAl + doff, (AL) + (size_t)(m0 + r) * 512 + kb + j); \
            cpasync16(sBh + doff, (WHp) + (size_t)(n0 + r) * 512 + kb + j); \
            cpasync16(sBl + doff, (WLp) + (size_t)(n0 + r) * 512 + kb + j); \
        } \
        CP_COMMIT(); \
    }; \
    load_chunk(0, 0); \
    for (int c = 0; c < 16; ++c) { \
        int buf = c & 1; \
        if (c < 15) load_chunk(c + 1, buf ^ 1); \
        if (c < 15) CP_WAIT(1); else CP_WAIT(0); \
        __syncthreads(); \
        u32 bofs = (u32)(buf * 128 * GPAD * 2); \
        _Pragma("unroll") \
        for (int s = 0; s < 2; ++s) { \
            int colb = (s * 16 + (lane >> 4) * 8) * 2; \
            u32 fa[2][4], fal[2][4]; \
            _Pragma("unroll") \
            for (int a = 0; a < 2; ++a) { \
                u32 ro = (u32)((wm * 32 + a * 16 + (lane & 15)) * GPAD * 2) + colb + bofs; \
                LDM4(fa[a],  sAh + ro); \
                LDM4(fal[a], sAl + ro); \
            } \
            _Pragma("unroll") \
            for (int p = 0; p < 4; ++p) { \
                u32 fbh[4], fbl[4]; \
                u32 ro = (u32)((wn * 64 + p * 16 + (lane & 15)) * GPAD * 2) + colb + bofs; \
                LDM4(fbh, sBh + ro); \
                LDM4(fbl, sBl + ro); \
                MMA_3TERM_P(acc, fa, fal, fbh, fbl, p); \
            } \
        } \
        __syncthreads(); \
    }

// ===================== generic GEMM =========================================
// MODE 0: plain fp32; 4: relu -> bf16 hi/lo row-major
template<int MODE>
__global__ __launch_bounds__(256, 2)
void gemm_mma(const bf16* __restrict__ ah, const bf16* __restrict__ al,
              const bf16* __restrict__ wh, const bf16* __restrict__ wl,
              const float* __restrict__ bias, float* __restrict__ out,
              bf16* __restrict__ outh, bf16* __restrict__ outl) {
    extern __shared__ bf16 sm[];
    bf16* pAh = sm;
    bf16* pAl = pAh + GARR;
    bf16* pBh = pAl + GARR;
    bf16* pBl = pBh + GARR;
    const int tid = threadIdx.x, lane = tid & 31, wid = tid >> 5;
    const int wm = wid & 3, wn = wid >> 2;
    const int m0 = blockIdx.x * 128, n0 = blockIdx.y * 128;

    GEMM_MAINLOOP(ah, al, wh, wl)

    int rg = m0 + wm * 32 + (lane >> 2);
    int cg = n0 + wn * 64 + (lane & 3) * 2;
    #pragma unroll
    for (int a = 0; a < 2; ++a)
        #pragma unroll
        for (int n = 0; n < 8; ++n) {
            int col = cg + n * 8;
            float2 bv = *(const float2*)&bias[col];
            #pragma unroll
            for (int hf = 0; hf < 2; ++hf) {
                int row = rg + a * 16 + hf * 8;
                float2 v = make_float2(acc[a][n][hf*2] + bv.x, acc[a][n][hf*2+1] + bv.y);
                if (MODE == 4) {
                    v.x = fmaxf(v.x, 0.f); v.y = fmaxf(v.y, 0.f);
                    bf16 hx, lx, hy, ly;
                    split1(v.x, hx, lx); split1(v.y, hy, ly);
                    __nv_bfloat162 hv = __halves2bfloat162(hx, hy);
                    __nv_bfloat162 lv = __halves2bfloat162(lx, ly);
                    size_t o = (size_t)row * 512 + col;
                    *(u32*)&outh[o] = *(u32*)&hv;
                    *(u32*)&outl[o] = *(u32*)&lv;
                } else {
                    *(float2*)&out[(size_t)row * 512 + col] = v;
                }
            }
        }
}

// ===================== fused QKV GEMM =======================================
// grid (64, 12): slot = by>>2 (0:Q 1:K 2:V), n-tile = by&3
__global__ __launch_bounds__(256, 2)
void qkv_mma(const bf16* __restrict__ ah, const bf16* __restrict__ al,
             const bf16* __restrict__ wh, const bf16* __restrict__ wl,
             const float* __restrict__ bq, const float* __restrict__ bk,
             const float* __restrict__ bv,
             float* __restrict__ outq, float* __restrict__ outk, float* __restrict__ outv,
             bf16* __restrict__ outqh, bf16* __restrict__ outkh) {
    extern __shared__ bf16 sm[];
    bf16* pAh = sm;
    bf16* pAl = pAh + GARR;
    bf16* pBh = pAl + GARR;
    bf16* pBl = pBh + GARR;
    const int tid = threadIdx.x, lane = tid & 31, wid = tid >> 5;
    const int wm = wid & 3, wn = wid >> 2;
    const int slot = blockIdx.y >> 2;
    const int m0 = blockIdx.x * 128, n0 = (blockIdx.y & 3) * 128;
    const bf16* whp = wh + (size_t)slot * DD * DD;
    const bf16* wlp = wl + (size_t)slot * DD * DD;
    const float* bias = (slot == 0) ? bq : (slot == 1) ? bk : bv;
    float* out = (slot == 0) ? outq : (slot == 1) ? outk : outv;
    bf16* outh = (slot == 0) ? outqh : outkh;

    GEMM_MAINLOOP(ah, al, whp, wlp)

    int rg = m0 + wm * 32 + (lane >> 2);
    int cg = n0 + wn * 64 + (lane & 3) * 2;
    #pragma unroll
    for (int a = 0; a < 2; ++a)
        #pragma unroll
        for (int n = 0; n < 8; ++n) {
            int col = cg + n * 8;
            float2 bvv = *(const float2*)&bias[col];
            #pragma unroll
            for (int hf = 0; hf < 2; ++hf) {
                int row = rg + a * 16 + hf * 8;
                float2 v = make_float2(acc[a][n][hf*2] + bvv.x, acc[a][n][hf*2+1] + bvv.y);
                int hh = col >> 6, dh = col & 63, b_ = row >> 11, l_ = row & 2047;
                size_t o = (((size_t)(b_*HH + hh))*LL + l_)*DH + dh;
                *(float2*)&out[o] = v;
                if (slot < 2) {
                    __nv_bfloat162 hv = __floats2bfloat162_rn(v.x, v.y);
                    *(u32*)&outh[o] = *(u32*)&hv;
                }
            }
        }
}

// ===================== M(q): 1-term bf16 warp MMA ==========================
#define MPAD 72
__global__ __launch_bounds__(256, 2)
void m_mma(const bf16* __restrict__ qh, const bf16* __restrict__ kh,
           const float* __restrict__ qf, const float* __restrict__ ksum,
           float* __restrict__ Mout) {
    extern __shared__ bf16 sm[];
    bf16* pK = sm;
    float* red = (float*)(pK + 2*128*MPAD);
    const int tid = threadIdx.x, lane = tid & 31, wid = tid >> 5;
    const int wm = wid & 3, wn = wid >> 2;
    const int bh = blockIdx.y, q0 = blockIdx.x * 128;
    const bf16* qhb = qh + (size_t)bh * LL * DH;
    const bf16* khb = kh + (size_t)bh * LL * DH;
    const u32 sK = smem_u32(pK);
    const u32 sQ = sK + 128 * MPAD * 2;

    auto load_k = [&](int t, int buf) {
        #pragma unroll
        for (int u = 0; u < 4; ++u) {
            int i = tid + u * 256;
            int r = i >> 3, j = (i & 7) * 8;
            cpasync16(sK + (u32)((buf * 128 * MPAD + r * MPAD + j) * 2),
                      khb + (size_t)(t * 128 + r) * 64 + j);
        }
        CP_COMMIT();
    };

    load_k(0, 0);
    #pragma unroll
    for (int u = 0; u < 4; ++u) {
        int i = tid + u * 256;
        int r = i >> 3, j = (i & 7) * 8;
        cpasync16(sQ + (u32)((r * MPAD + j) * 2), qhb + (size_t)(q0 + r) * 64 + j);
    }
    CP_COMMIT();
    CP_WAIT(0);
    __syncthreads();

    u32 fq[4][2][4];
    #pragma unroll
    for (int s = 0; s < 4; ++s) {
        int colb = (s * 16 + (lane >> 4) * 8) * 2;
        #pragma unroll
        for (int a = 0; a < 2; ++a) {
            u32 ro = (u32)((wm * 32 + a * 16 + (lane & 15)) * MPAD * 2) + colb;
            LDM4(fq[s][a], sQ + ro);
        }
    }
    __syncthreads();

    float rmax[2][2];
    rmax[0][0] = rmax[0][1] = rmax[1][0] = rmax[1][1] = -INFINITY;

    for (int t = 0; t < 16; ++t) {
        int buf = t & 1;
        if (t < 15) load_k(t + 1, buf ^ 1);
        if (t < 15) CP_WAIT(1); else CP_WAIT(0);
        __syncthreads();
        float acc[2][8][4];
        #pragma unroll
        for (int a = 0; a < 2; ++a)
            #pragma unroll
            for (int n = 0; n < 8; ++n)
                #pragma unroll
                for (int j = 0; j < 4; ++j) acc[a][n][j] = 0.f;
        u32 bofs = (u32)(buf * 128 * MPAD * 2);
        #pragma unroll
        for (int s = 0; s < 4; ++s) {
            int colb = (s * 16 + (lane >> 4) * 8) * 2;
            #pragma unroll
            for (int p = 0; p < 4; ++p) {
                u32 fb[4];
                u32 ro = (u32)((wn * 64 + p * 16 + (lane & 15)) * MPAD * 2) + colb + bofs;
                LDM4(fb, sK + ro);
                #pragma unroll
                for (int a = 0; a < 2; ++a) {
                    MMA(acc[a][2*p],   fq[s][a], fb[0], fb[2]);
                    MMA(acc[a][2*p+1], fq[s][a], fb[1], fb[3]);
                }
            }
        }
        #pragma unroll
        for (int a = 0; a < 2; ++a)
            #pragma unroll
            for (int n = 0; n < 8; ++n) {
                rmax[a][0] = fmaxf(rmax[a][0], fmaxf(acc[a][n][0], acc[a][n][1]));
                rmax[a][1] = fmaxf(rmax[a][1], fmaxf(acc[a][n][2], acc[a][n][3]));
            }
        __syncthreads();
    }

    #pragma unroll
    for (int a = 0; a < 2; ++a)
        #pragma unroll
        for (int hf = 0; hf < 2; ++hf) {
            float v = rmax[a][hf];
            v = fmaxf(v, __shfl_xor_sync(0xffffffffu, v, 1));
            v = fmaxf(v, __shfl_xor_sync(0xffffffffu, v, 2));
            rmax[a][hf] = v;
        }
    if ((lane & 3) == 0) {
        #pragma unroll
        for (int a = 0; a < 2; ++a)
            #pragma unroll
            for (int hf = 0; hf < 2; ++hf)
                red[wn * 128 + wm * 32 + a * 16 + hf * 8 + (lane >> 2)] = rmax[a][hf];
    }
    __syncthreads();
    if (tid < 128) {
        float m = fmaxf(red[tid], red[128 + tid]);
        const float* ks = ksum + bh * DH;
        const float* qrow = qf + ((size_t)bh * LL + q0 + tid) * DH;
        float dot = 0.f;
        #pragma unroll
        for (int d = 0; d < 64; ++d) dot += qrow[d] * ks[d];
        Mout[bh * LL + q0 + tid] = (m - dot * (1.f / LL)) * SCALE;
    }
}

// ===================== per-(b,h) sums (wide grid + atomics) ================
// grid = BH*16 blocks; each handles 128 rows of one (b,h)
__global__ void sums_part(const float* __restrict__ k, const float* __restrict__ v,
                          float* __restrict__ ksum, float* __restrict__ vsum) {
    int bh = blockIdx.x >> 4, chunk = blockIdx.x & 15;
    int tid = threadIdx.x;                 // 256
    int d = tid & 63, c = tid >> 6;        // 4 rows in flight
    const float* kb = k + ((size_t)bh * LL + chunk * 128) * DH + d;
    const float* vb = v + ((size_t)bh * LL + chunk * 128) * DH + d;
    float ks = 0.f, vs = 0.f;
    for (int l = c; l < 128; l += 4) { ks += kb[(size_t)l*DH]; vs += vb[(size_t)l*DH]; }
    __shared__ float rk[4][64], rv[4][64];
    rk[c][d] = ks; rv[c][d] = vs;
    __syncthreads();
    if (tid < 64) {
        float a = rk[0][tid] + rk[1][tid] + rk[2][tid] + rk[3][tid];
        float m = rv[0][tid] + rv[1][tid] + rv[2][tid] + rv[3][tid];
        atomicAdd(&ksum[bh*DH + tid], a);
        atomicAdd(&vsum[bh*DH + tid], m);
    }
}

__global__ void vmean_fin(const float* __restrict__ vsum, float* __restrict__ vmean) {
    int i = blockIdx.x * 256 + threadIdx.x;     // BH*DH = 2048
    if (i < BH*DH) vmean[i] = vsum[i] * (1.f / LL);
}

// ===================== top-U selection =====================================
__global__ void topk_kernel(const float* __restrict__ M, int* __restrict__ idxout) {
    int bh = blockIdx.x, tid = threadIdx.x;
    __shared__ float sm[LL];
    __shared__ float bvv[256];
    __shared__ int   bii[256];
    for (int l = tid; l < LL; l += 256) sm[l] = M[bh*LL + l];
    __syncthreads();
    for (int it = 0; it < UU; ++it) {
        float best = -INFINITY; int bidx = LL;
        for (int l = tid; l < LL; l += 256) {
            float v = sm[l];
            if (v > best || (v == best && l < bidx)) { best = v; bidx = l; }
        }
        bvv[tid] = best; bii[tid] = bidx;
        __syncthreads();
        for (int s = 128; s > 0; s >>= 1) {
            if (tid < s) {
                if (bvv[tid+s] > bvv[tid] || (bvv[tid+s] == bvv[tid] && bii[tid+s] < bii[tid])) {
                    bvv[tid] = bvv[tid+s]; bii[tid] = bii[tid+s];
                }
            }
            __syncthreads();
        }
        if (tid == 0) { idxout[bh*UU + it] = bii[0]; sm[bii[0]] = -INFINITY; }
        __syncthreads();
    }
}

// ===================== attention (8 queries / block) =======================
__global__ __launch_bounds__(256, 2)
void attn_kernel(const float* __restrict__ q, const float* __restrict__ k,
                 const float* __restrict__ v, const int* __restrict__ idx,
                 float* __restrict__ upd) {
    extern __shared__ float sbuf[];
    float* sc   = sbuf;
    float* qv   = sbuf + 8*2048;
    float* red  = qv + 512;
    float* sinv = red + 2048;
    int bh = blockIdx.x, u0 = blockIdx.y * 8;
    int tid = threadIdx.x;
    const float* kb = k + (size_t)bh * LL * DH;
    const float* vb = v + (size_t)bh * LL * DH;

    for (int i = tid; i < 8*64; i += 256) {
        int u = i >> 6, d = i & 63;
        int lq = idx[bh*UU + u0 + u];
        qv[i] = q[((size_t)bh*LL + lq)*DH + d];
    }
    __syncthreads();

    for (int l = tid; l < LL; l += 256) {
        const float4* kr = (const float4*)(kb + (size_t)l*DH);
        float acc[8];
        #pragma unroll
        for (int u = 0; u < 8; ++u) acc[u] = 0.f;
        #pragma unroll
        for (int t = 0; t < 16; ++t) {
            float4 kv = kr[t];
            #pragma unroll
            for (int u = 0; u < 8; ++u) {
                float4 qq = *(const float4*)&qv[u*64 + t*4];
                acc[u] += kv.x*qq.x + kv.y*qq.y + kv.z*qq.z + kv.w*qq.w;
            }
        }
        #pragma unroll
        for (int u = 0; u < 8; ++u) sc[u*2048 + l] = acc[u] * SCALE;
    }
    __syncthreads();

    {
        int u = tid >> 5, lane = tid & 31;
        float m = -INFINITY;
        for (int l = lane; l < LL; l += 32) m = fmaxf(m, sc[u*2048 + l]);
        #pragma unroll
        for (int o = 16; o > 0; o >>= 1) m = fmaxf(m, __shfl_xor_sync(0xffffffffu, m, o));
        float s = 0.f;
        for (int l = lane; l < LL; l += 32) {
            float e = __expf(sc[u*2048 + l] - m);
            sc[u*2048 + l] = e; s += e;
        }
        #pragma unroll
        for (int o = 16; o > 0; o >>= 1) s += __shfl_xor_sync(0xffffffffu, s, o);
        if (lane == 0) sinv[u] = 1.f / s;
    }
    __syncthreads();

    int d = tid & 63, lc = tid >> 6;
    float acc[8];
    #pragma unroll
    for (int u = 0; u < 8; ++u) acc[u] = 0.f;
    for (int l = lc; l < LL; l += 4) {
        float vv = vb[(size_t)l*DH + d];
        #pragma unroll
        for (int u = 0; u < 8; ++u) acc[u] += sc[u*2048 + l] * vv;
    }
    #pragma unroll
    for (int u = 0; u < 8; ++u) red[(lc*8 + u)*64 + d] = acc[u];
    __syncthreads();
    if (tid < 64) {
        #pragma unroll
        for (int u = 0; u < 8; ++u) {
            float t = red[u*64 + tid] + red[(8+u)*64 + tid] +
                      red[(16+u)*64 + tid] + red[(24+u)*64 + tid];
            upd[((size_t)bh*UU + u0 + u)*DH + tid] = t * sinv[u];
        }
    }
}

// ===================== Wo via base + sparse corrections ====================
__global__ void base_kernel(const float* __restrict__ vmean, const float* __restrict__ Wo,
                            const float* __restrict__ bo, float* __restrict__ base) {
    int b = blockIdx.x, n = threadIdx.x;
    const float* vm = vmean + b * 512;
    float acc = bo[n];
    for (int kk = 0; kk < 512; ++kk)
        acc += vm[kk] * Wo[(size_t)kk*512 + n];
    base[b*512 + n] = acc;
}

__global__ void corr_kernel(const float* __restrict__ upd, const float* __restrict__ vmean,
                            const float* __restrict__ Wo, const int* __restrict__ idx,
                            float* __restrict__ delta) {
    int blk = blockIdx.x;
    int bh = blk / UU, u = blk % UU;
    int h = bh & 7, b = bh >> 3;
    __shared__ float du[64];
    int tid = threadIdx.x;
    if (tid < 64) du[tid] = upd[(size_t)blk*64 + tid] - vmean[bh*64 + tid];
    __syncthreads();
    int l = idx[bh*UU + u];
    float* drow = delta + ((size_t)b*LL + l)*DD;
    const float* wrow = Wo + (size_t)h*64*512;
    #pragma unroll
    for (int half = 0; half < 2; ++half) {
        int n = tid + half*256;
        float acc = 0.f;
        #pragma unroll 8
        for (int d = 0; d < 64; ++d) acc += du[d] * wrow[(size_t)d*512 + n];
        atomicAdd(&drow[n], acc);
    }
}

// ===================== residual + LayerNorm (fused splits) =================
__global__ void addln_base_kernel(float* h, const float* __restrict__ delta,
                                  const float* __restrict__ base,
                                  const float* __restrict__ g, const float* __restrict__ b,
                                  bf16* __restrict__ sh, bf16* __restrict__ sl) {
    int row = blockIdx.x, tid = threadIdx.x;
    int bb_ = row >> 11;
    float* hr = h + (size_t)row * DD;
    const float* dr = delta + (size_t)row * DD;
    const float* br = base + bb_ * DD;
    __shared__ float rbuf[8];
    __shared__ float sh_mean, sh_var;
    float s0 = hr[tid]       + dr[tid]       + br[tid];
    float s1 = hr[tid + 256] + dr[tid + 256] + br[tid + 256];
    float s = s0 + s1;
    for (int o = 16; o > 0; o >>= 1) s += __shfl_down_sync(0xffffffffu, s, o);
    if ((tid & 31) == 0) rbuf[tid >> 5] = s;
    __syncthreads();
    if (tid == 0) {
        float t = 0.f;
        #pragma unroll
        for (int i = 0; i < 8; ++i) t += rbuf[i];
        sh_mean = t * (1.f / DD);
    }
    __syncthreads();
    float mval = sh_mean;
    float d0 = s0 - mval, d1 = s1 - mval;
    float vv = d0*d0 + d1*d1;
    for (int o = 16; o > 0; o >>= 1) vv += __shfl_down_sync(0xffffffffu, vv, o);
    if ((tid & 31) == 0) rbuf[tid >> 5] = vv;
    __syncthreads();
    if (tid == 0) {
        float t = 0.f;
        #pragma unroll
        for (int i = 0; i < 8; ++i) t += rbuf[i];
        sh_var = t * (1.f / DD);
    }
    __syncthreads();
    float inv = rsqrtf(sh_var + 1e-5f);
    float o0 = d0 * inv * g[tid]       + b[tid];
    float o1 = d1 * inv * g[tid + 256] + b[tid + 256];
    hr[tid] = o0; hr[tid + 256] = o1;
    bf16 hh, ll;
    split1(o0, hh, ll); sh[(size_t)row*DD + tid] = hh;       sl[(size_t)row*DD + tid] = ll;
    split1(o1, hh, ll); sh[(size_t)row*DD + tid + 256] = hh; sl[(size_t)row*DD + tid + 256] = ll;
}

template<int SPLIT>
__global__ void addln_kernel(float* h, const float* __restrict__ a,
                             const float* __restrict__ g, const float* __restrict__ b,
                             bf16* __restrict__ sh, bf16* __restrict__ sl) {
    int row = blockIdx.x, tid = threadIdx.x;
    float* hr = h + (size_t)row * DD;
    const float* ar = a + (size_t)row * DD;
    __shared__ float rbuf[8];
    __shared__ float sh_mean, sh_var;
    float s0 = hr[tid]       + ar[tid];
    float s1 = hr[tid + 256] + ar[tid + 256];
    float s = s0 + s1;
    for (int o = 16; o > 0; o >>= 1) s += __shfl_down_sync(0xffffffffu, s, o);
    if ((tid & 31) == 0) rbuf[tid >> 5] = s;
    __syncthreads();
    if (tid == 0) {
        float t = 0.f;
        #pragma unroll
        for (int i = 0; i < 8; ++i) t += rbuf[i];
        sh_mean = t * (1.f / DD);
    }
    __syncthreads();
    float mval = sh_mean;
    float d0 = s0 - mval, d1 = s1 - mval;
    float vv = d0*d0 + d1*d1;
    for (int o = 16; o > 0; o >>= 1) vv += __shfl_down_sync(0xffffffffu, vv, o);
    if ((tid & 31) == 0) rbuf[tid >> 5] = vv;
    __syncthreads();
    if (tid == 0) {
        float t = 0.f;
        #pragma unroll
        for (int i = 0; i < 8; ++i) t += rbuf[i];
        sh_var = t * (1.f / DD);
    }
    __syncthreads();
    float inv = rsqrtf(sh_var + 1e-5f);
    float o0 = d0 * inv * g[tid]       + b[tid];
    float o1 = d1 * inv * g[tid + 256] + b[tid + 256];
    hr[tid] = o0; hr[tid + 256] = o1;
    if (SPLIT) {
        bf16 hh, ll;
        split1(o0, hh, ll); sh[(size_t)row*DD + tid] = hh;       sl[(size_t)row*DD + tid] = ll;
        split1(o1, hh, ll); sh[(size_t)row*DD + tid + 256] = hh; sl[(size_t)row*DD + tid + 256] = ll;
    }
}

// ===================== final projection ====================================
__global__ void proj_kernel(const float* __restrict__ h, const float* __restrict__ pw,
                            const float* __restrict__ pb, float* __restrict__ out) {
    int bp = blockIdx.x;
    int b = bp / PP, p = bp % PP;
    int l = LL - PP + p;
    int tid = threadIdx.x;
    const float* hr = h + ((size_t)b*LL + l)*DD;
    float acc[EE];
    #pragma unroll
    for (int e = 0; e < EE; ++e) acc[e] = 0.f;
    for (int kk = tid; kk < DD; kk += 64) {
        float hv = hr[kk];
        #pragma unroll
        for (int e = 0; e < EE; ++e) acc[e] += hv * pw[kk*EE + e];
    }
    __shared__ float red[EE][64];
    #pragma unroll
    for (int e = 0; e < EE; ++e) red[e][tid] = acc[e];
    __syncthreads();
    if (tid < EE) {
        float t = 0.f;
        for (int i = 0; i < 64; ++i) t += red[tid][i];
        out[(size_t)bp * EE + tid] = t + pb[tid];
    }
}

// ===================== host driver =========================================
#define SMEM_G_BYTES (4 * GARR * 2)
#define SMEM_M_BYTES (2*128*MPAD*2 + 1024)
#define SMEM_A_BYTES ((8*2048 + 512 + 2048 + 8) * 4)

extern "C" void kernel_launch(void* const* d_in, const int* in_sizes, int n_in,
                              void* d_out, int out_size) {
    const float* x      = (const float*)d_in[0];
    const float* emb_w  = (const float*)d_in[1];
    const float* emb_b  = (const float*)d_in[2];
    const float* Wq     = (const float*)d_in[3];
    const float* bq     = (const float*)d_in[4];
    const float* Wk     = (const float*)d_in[5];
    const float* bk     = (const float*)d_in[6];
    const float* Wv     = (const float*)d_in[7];
    const float* bv     = (const float*)d_in[8];
    const float* Wo     = (const float*)d_in[9];
    const float* bo     = (const float*)d_in[10];
    const float* W1     = (const float*)d_in[11];
    const float* b1     = (const float*)d_in[12];
    const float* W2     = (const float*)d_in[13];
    const float* b2     = (const float*)d_in[14];
    const float* ln1_g  = (const float*)d_in[15];
    const float* ln1_b  = (const float*)d_in[16];
    const float* ln2_g  = (const float*)d_in[17];
    const float* ln2_b  = (const float*)d_in[18];
    const float* proj_w = (const float*)d_in[19];
    const float* proj_b = (const float*)d_in[20];

    static float *p_h = nullptr, *p_q, *p_k, *p_v, *p_t2, *p_M,
                 *p_ksum, *p_vsum, *p_vmean, *p_upd, *p_base;
    static bf16 *p_ah, *p_al, *p_bh, *p_bl, *p_wh, *p_wl, *p_qh, *p_kh;
    static int *p_idx;
    if (!p_h) {
        cudaGetSymbolAddress((void**)&p_h,    g_h);
        cudaGetSymbolAddress((void**)&p_q,    g_q);
        cudaGetSymbolAddress((void**)&p_k,    g_k);
        cudaGetSymbolAddress((void**)&p_v,    g_v);
        cudaGetSymbolAddress((void**)&p_t2,   g_t2);
        cudaGetSymbolAddress((void**)&p_M,    g_M);
        cudaGetSymbolAddress((void**)&p_idx,  g_idx);
        cudaGetSymbolAddress((void**)&p_ksum, g_ksum);
        cudaGetSymbolAddress((void**)&p_vsum, g_vsum);
        cudaGetSymbolAddress((void**)&p_vmean,g_vmean);
        cudaGetSymbolAddress((void**)&p_upd,  g_upd);
        cudaGetSymbolAddress((void**)&p_base, g_base);
        cudaGetSymbolAddress((void**)&p_ah,   g_ah);
        cudaGetSymbolAddress((void**)&p_al,   g_al);
        cudaGetSymbolAddress((void**)&p_bh,   g_bh);
        cudaGetSymbolAddress((void**)&p_bl,   g_bl);
        cudaGetSymbolAddress((void**)&p_wh,   g_wh);
        cudaGetSymbolAddress((void**)&p_wl,   g_wl);
        cudaGetSymbolAddress((void**)&p_qh,   g_qh);
        cudaGetSymbolAddress((void**)&p_kh,   g_kh);
        cudaFuncSetAttribute(gemm_mma<0>, cudaFuncAttributeMaxDynamicSharedMemorySize, SMEM_G_BYTES);
        cudaFuncSetAttribute(gemm_mma<4>, cudaFuncAttributeMaxDynamicSharedMemorySize, SMEM_G_BYTES);
        cudaFuncSetAttribute(qkv_mma,     cudaFuncAttributeMaxDynamicSharedMemorySize, SMEM_G_BYTES);
        cudaFuncSetAttribute(m_mma,       cudaFuncAttributeMaxDynamicSharedMemorySize, SMEM_M_BYTES);
        cudaFuncSetAttribute(attn_kernel, cudaFuncAttributeMaxDynamicSharedMemorySize, SMEM_A_BYTES);
    }

    embed_kernel<<<(BB*LL*DD)/256, 256>>>(x, emb_w, emb_b, p_h, p_ah, p_al);

    dim3 gg(MROWS/128, DD/128);
    dim3 wsg(16, 16, 5), wsb(32, 8);
    for (int il = 0; il < NL; ++il) {
        const size_t wo = (size_t)il * DD * DD;
        const size_t boff = (size_t)il * DD;
        wsplit_kernel<<<wsg, wsb>>>(Wq + wo, Wk + wo, Wv + wo, W1 + wo, W2 + wo, p_wh, p_wl);
        qkv_mma<<<dim3(MROWS/128, 12), 256, SMEM_G_BYTES>>>(
            p_ah, p_al, p_wh, p_wl, bq + boff, bk + boff, bv + boff,
            p_q, p_k, p_v, p_qh, p_kh);
        cudaMemsetAsync(p_ksum, 0, BH*DH*sizeof(float));
        cudaMemsetAsync(p_vsum, 0, BH*DH*sizeof(float));
        sums_part<<<BH*16, 256>>>(p_k, p_v, p_ksum, p_vsum);
        vmean_fin<<<(BH*DH+255)/256, 256>>>(p_vsum, p_vmean);
        m_mma<<<dim3(LL/128, BH), 256, SMEM_M_BYTES>>>(p_qh, p_kh, p_q, p_ksum, p_M);
        topk_kernel<<<BH, 256>>>(p_M, p_idx);
        attn_kernel<<<dim3(BH, UU/8), 256, SMEM_A_BYTES>>>(p_q, p_k, p_v, p_idx, p_upd);
        base_kernel<<<BB, 512>>>(p_vmean, Wo + wo, bo + boff, p_base);
        cudaMemsetAsync(p_t2, 0, (size_t)BB*LL*DD*sizeof(float));
        corr_kernel<<<BH*UU, 256>>>(p_upd, p_vmean, Wo + wo, p_idx, p_t2);
        addln_base_kernel<<<MROWS, 256>>>(p_h, p_t2, p_base, ln1_g + boff, ln1_b + boff, p_ah, p_al);
        gemm_mma<4><<<gg, 256, SMEM_G_BYTES>>>(p_ah, p_al, p_wh + 3*DD*DD, p_wl + 3*DD*DD, b1 + boff, p_t2, p_bh, p_bl);
        gemm_mma<0><<<gg, 256, SMEM_G_BYTES>>>(p_bh, p_bl, p_wh + 4*DD*DD, p_wl + 4*DD*DD, b2 + boff, p_t2, p_bh, p_bl);
        if (il < NL - 1)
            addln_kernel<1><<<MROWS, 256>>>(p_h, p_t2, ln2_g + boff, ln2_b + boff, p_ah, p_al);
        else
            addln_kernel<0><<<MROWS, 256>>>(p_h, p_t2, ln2_g + boff, ln2_b + boff, p_ah, p_al);
    }

    proj_kernel<<<BB*PP, 64>>>(p_h, proj_w, proj_b, (float*)d_out);
}